// round 15
// baseline (speedup 1.0000x reference)
#include <cuda_runtime.h>
#include <cuda_fp16.h>
#include <math.h>
#include <stdint.h>

// Problem constants
#define CL   12
#define CD   768
#define CH   12
#define CF   3072
#define CB   8
#define CS   784
#define CHD  64
#define CBS  (CB*CS)          // 6272 rows
#define CEPS 1e-6f
#define QKVD 2304             // packed q|k|v row width

// ---------------------------------------------------------------------------
// Scratch (device globals; no allocations allowed)
// ---------------------------------------------------------------------------
__device__ float g_h [CBS*CD];

__device__ __half g_yh  [CBS*CD];
__device__ __half g_qkv [(size_t)CBS*QKVD];
__device__ __half g_ctxh[CBS*CD];
__device__ __half g_mlph[(size_t)CBS*CF];

// transposed fp16 weights: qkv packed [L][2304][768]; others [L][N][K]
__device__ __half g_wqkvt[(size_t)CL*QKVD*CD];
__device__ __half g_wot[CL*CD*CD];
__device__ __half g_w1t[(size_t)CL*CD*CF];
__device__ __half g_w2t[(size_t)CL*CD*CF];
__device__ float  g_bqkv[CL*QKVD];

// ---------------------------------------------------------------------------
// helpers
// ---------------------------------------------------------------------------
__device__ __forceinline__ uint32_t smem_u32(const void* p) {
    return (uint32_t)__cvta_generic_to_shared(p);
}
__device__ __forceinline__ uint32_t pack2h(float a, float b) {
    __half2 t = __floats2half2_rn(a, b);
    return *reinterpret_cast<uint32_t*>(&t);
}

__device__ __forceinline__ void mma16f(float* c, const uint32_t* a, const uint32_t* b) {
    asm("mma.sync.aligned.m16n8k16.row.col.f32.f16.f16.f32 "
        "{%0,%1,%2,%3},{%4,%5,%6,%7},{%8,%9},{%0,%1,%2,%3};"
        : "+f"(c[0]), "+f"(c[1]), "+f"(c[2]), "+f"(c[3])
        : "r"(a[0]), "r"(a[1]), "r"(a[2]), "r"(a[3]), "r"(b[0]), "r"(b[1]));
}

#define CP16(dst, src) \
    asm volatile("cp.async.cg.shared.global [%0], [%1], 16;" \
                 :: "r"(dst), "l"(src) : "memory")

#define LDMX4(r, addr) \
    asm volatile("ldmatrix.sync.aligned.m8n8.x4.shared.b16 {%0,%1,%2,%3}, [%4];" \
                 : "=r"((r)[0]), "=r"((r)[1]), "=r"((r)[2]), "=r"((r)[3]) \
                 : "r"(addr))

#define LDMX4T(r, addr) \
    asm volatile("ldmatrix.sync.aligned.m8n8.x4.trans.shared.b16 {%0,%1,%2,%3}, [%4];" \
                 : "=r"((r)[0]), "=r"((r)[1]), "=r"((r)[2]), "=r"((r)[3]) \
                 : "r"(addr))

#define EX2H2(out, in) \
    asm("ex2.approx.f16x2 %0, %1;" : "=r"(out) : "r"(in))

// ---------------------------------------------------------------------------
// Block reduction (256 threads)
// ---------------------------------------------------------------------------
__device__ __forceinline__ float bsum(float v) {
    __shared__ float red[32];
    #pragma unroll
    for (int o = 16; o; o >>= 1) v += __shfl_xor_sync(0xffffffffu, v, o);
    if ((threadIdx.x & 31) == 0) red[threadIdx.x >> 5] = v;
    __syncthreads();
    float t = (threadIdx.x < (blockDim.x >> 5)) ? red[threadIdx.x] : 0.0f;
    if (threadIdx.x < 32) {
        #pragma unroll
        for (int o = 16; o; o >>= 1) t += __shfl_xor_sync(0xffffffffu, t, o);
        if (threadIdx.x == 0) red[0] = t;
    }
    __syncthreads();
    float r = red[0];
    __syncthreads();
    return r;
}

// ---------------------------------------------------------------------------
// Merged weight prep (unchanged)
// ---------------------------------------------------------------------------
__global__ void __launch_bounds__(256) prep_kernel(
    const float* __restrict__ wq, const float* __restrict__ wk,
    const float* __restrict__ wv, const float* __restrict__ wo,
    const float* __restrict__ w1, const float* __restrict__ w2,
    __half* __restrict__ wqkvt, __half* __restrict__ wot,
    __half* __restrict__ w1t,   __half* __restrict__ w2t)
{
    __shared__ float t[64][33];
    int l = blockIdx.y, tile = blockIdx.x;
    const float* W;
    __half* T;
    int K, N, n0, k0;

    if (tile < 1152) {
        int seg = tile / 288, tt = tile % 288;
        K = CD; N = CD;
        n0 = (tt % 24) * 32; k0 = (tt / 24) * 64;
        if (seg < 3) {
            W = (seg == 0) ? wq : (seg == 1) ? wk : wv;
            W += (size_t)l * CD * CD;
            T = wqkvt + (size_t)l * QKVD * CD + (size_t)(seg * CD + n0) * CD + k0;
        } else {
            W = wo + (size_t)l * CD * CD;
            T = wot + (size_t)l * CD * CD + (size_t)n0 * CD + k0;
        }
    } else if (tile < 2304) {
        int tt = tile - 1152;
        K = CD; N = CF;
        n0 = (tt % 96) * 32; k0 = (tt / 96) * 64;
        W = w1 + (size_t)l * CD * CF;
        T = w1t + (size_t)l * CD * CF + (size_t)n0 * CD + k0;
    } else {
        int tt = tile - 2304;
        K = CF; N = CD;
        n0 = (tt % 24) * 32; k0 = (tt / 24) * 64;
        W = w2 + (size_t)l * CD * CF;
        T = w2t + (size_t)l * CD * CF + (size_t)n0 * CF + k0;
    }

    int tid = threadIdx.x, lane = tid & 31, w = tid >> 5;
    #pragma unroll
    for (int i = 0; i < 2; i++) {
        int idx = tid + 256 * i;
        int row = idx >> 3;
        int c4  = (idx & 7) << 2;
        float4 v = *(const float4*)(W + (size_t)(k0 + row) * N + n0 + c4);
        t[row][c4 + 0] = v.x; t[row][c4 + 1] = v.y;
        t[row][c4 + 2] = v.z; t[row][c4 + 3] = v.w;
    }
    __syncthreads();
    #pragma unroll
    for (int pass = 0; pass < 4; pass++) {
        int n = w + pass * 8;
        uint32_t p = pack2h(t[2 * lane][n], t[2 * lane + 1][n]);
        *(uint32_t*)(T + (size_t)n * K + 2 * lane) = p;
    }
}

// pack qkv biases: [L][2304] = bq | bk | bv
__global__ void __launch_bounds__(256) pack_bias_kernel(
    const float* __restrict__ bq, const float* __restrict__ bk,
    const float* __restrict__ bv, float* __restrict__ out)
{
    int l = blockIdx.x;
    for (int i = threadIdx.x; i < QKVD; i += 256) {
        float v = (i < CD) ? bq[l * CD + i]
                : (i < 2 * CD) ? bk[l * CD + i - CD]
                : bv[l * CD + i - 2 * CD];
        out[l * QKVD + i] = v;
    }
}

// ---------------------------------------------------------------------------
// LayerNorm -> fp32 out (final) — vectorized
// ---------------------------------------------------------------------------
__global__ void __launch_bounds__(256) ln_kernel(
    const float* __restrict__ in, float* __restrict__ out,
    const float* __restrict__ gs, const float* __restrict__ gb)
{
    int tid = threadIdx.x;
    const float4* x4 = (const float4*)(in + (size_t)blockIdx.x * CD);
    float4 v = make_float4(0.f, 0.f, 0.f, 0.f);
    if (tid < 192) v = x4[tid];
    float mean = bsum(v.x + v.y + v.z + v.w) * (1.0f / CD);
    float c0 = v.x - mean, c1 = v.y - mean, c2 = v.z - mean, c3 = v.w - mean;
    float sq = (tid < 192) ? (c0*c0 + c1*c1 + c2*c2 + c3*c3) : 0.0f;
    float var = bsum(sq) * (1.0f / CD);
    float r = rsqrtf(var + CEPS);
    if (tid < 192) {
        float4 g4 = ((const float4*)gs)[tid];
        float4 b4 = ((const float4*)gb)[tid];
        float4 o4 = make_float4(c0 * r * g4.x + b4.x, c1 * r * g4.y + b4.y,
                                c2 * r * g4.z + b4.z, c3 * r * g4.w + b4.w);
        ((float4*)(out + (size_t)blockIdx.x * CD))[tid] = o4;
    }
}

// LayerNorm -> fp16 — vectorized
__global__ void __launch_bounds__(256) ln_h_kernel(
    const float* __restrict__ in, __half* __restrict__ oh,
    const float* __restrict__ gs, const float* __restrict__ gb)
{
    int tid = threadIdx.x;
    const float4* x4 = (const float4*)(in + (size_t)blockIdx.x * CD);
    float4 v = make_float4(0.f, 0.f, 0.f, 0.f);
    if (tid < 192) v = x4[tid];
    float mean = bsum(v.x + v.y + v.z + v.w) * (1.0f / CD);
    float c0 = v.x - mean, c1 = v.y - mean, c2 = v.z - mean, c3 = v.w - mean;
    float sq = (tid < 192) ? (c0*c0 + c1*c1 + c2*c2 + c3*c3) : 0.0f;
    float var = bsum(sq) * (1.0f / CD);
    float r = rsqrtf(var + CEPS);
    if (tid < 192) {
        float4 g4 = ((const float4*)gs)[tid];
        float4 b4 = ((const float4*)gb)[tid];
        uint2 o2;
        o2.x = pack2h(c0 * r * g4.x + b4.x, c1 * r * g4.y + b4.y);
        o2.y = pack2h(c2 * r * g4.z + b4.z, c3 * r * g4.w + b4.w);
        ((uint2*)(oh + (size_t)blockIdx.x * CD))[tid] = o2;
    }
}

// ---------------------------------------------------------------------------
// fp16 GEMM: C = A @ B^T (+bias/gelu/res). A[M][K], B[N][K] fp16.
// CTA tile 128x128, 128 threads = 4 warps, warp tile 64x64, KT=64,
// 3-stage cp.async, 2 CTAs/SM (smem 110.6KB/CTA; regs free up to 256 so
// ptxas can software-pipeline fragment loads). Per k16-step per warp:
// 8 ldmatrix.x4 + 32 HMMA (density 4.0).
// OUTM_: 0 = fp32 C, 2 = fp16 Ch
// ---------------------------------------------------------------------------
#define GST    36864
#define GSMEM3 (3*GST)

template<int GELU_, int RES_, int OUTM_>
__global__ void __launch_bounds__(128) gemm_fp16(
    const __half* __restrict__ Ah, const __half* __restrict__ Bh,
    const float* __restrict__ bias, const float* __restrict__ R,
    float* __restrict__ C, __half* __restrict__ Ch,
    int N, int K)
{
    extern __shared__ char smem[];
    const int tid = threadIdx.x, lane = tid & 31, wid = tid >> 5;
    const int bm = blockIdx.y * 128, bn = blockIdx.x * 128;
    const int wm = (wid >> 1) * 64, wn = (wid & 1) * 64;
    const int lr = lane >> 2, lc = lane & 3;
    const uint32_t sb = smem_u32(smem);

    const uint32_t a_off = (uint32_t)((wm + (lane & 15)) * 144 + (lane >> 4) * 16);
    const uint32_t b_off = (uint32_t)(18432 +
        (wn + ((lane >> 4) & 1) * 8 + (lane & 7)) * 144 + ((lane >> 3) & 1) * 16);

    auto fill = [&](int kt, int s) {
        int k0 = kt << 6;
        uint32_t stg = sb + s * GST;
        #pragma unroll
        for (int i = 0; i < 16; i++) {
            int idx = tid + 128 * i;              // 0..2047
            int arr = idx >> 10;                  // 0:A 1:B
            int c = idx & 1023;
            int row = c >> 3, ch = c & 7;
            const __half* g = (arr == 0) ? Ah : Bh;
            int rb = (arr == 0) ? bm : bn;
            const __half* src = g + (size_t)(rb + row) * K + k0 + ch * 8;
            uint32_t dst = stg + arr * 18432 + row * 144 + ch * 16;
            CP16(dst, src);
        }
        asm volatile("cp.async.commit_group;" ::: "memory");
    };

    float acc[4][8][4];
    #pragma unroll
    for (int mi = 0; mi < 4; mi++)
        #pragma unroll
        for (int ni = 0; ni < 8; ni++)
            #pragma unroll
            for (int e = 0; e < 4; e++) acc[mi][ni][e] = 0.0f;

    int NT = K >> 6;
    fill(0, 0);
    fill(1, 1);

    for (int kt = 0; kt < NT; kt++) {
        int s = kt % 3;
        asm volatile("cp.async.wait_group 1;" ::: "memory");
        __syncthreads();
        uint32_t stg = sb + s * GST;

        // issue next-tile loads first so LSU/memory latency overlaps MMAs
        if (kt + 2 < NT) fill(kt + 2, (kt + 2) % 3);
        else asm volatile("cp.async.commit_group;" ::: "memory");

        #pragma unroll
        for (int ks = 0; ks < 4; ks++) {
            uint32_t kb = ks * 32;
            uint32_t ah[4][4], bb[4][4];
            #pragma unroll
            for (int mi = 0; mi < 4; mi++)
                LDMX4(ah[mi], stg + a_off + mi * (16 * 144) + kb);
            #pragma unroll
            for (int nj = 0; nj < 4; nj++)
                LDMX4(bb[nj], stg + b_off + nj * (16 * 144) + kb);
            #pragma unroll
            for (int mi = 0; mi < 4; mi++)
                #pragma unroll
                for (int ni = 0; ni < 8; ni++)
                    mma16f(acc[mi][ni], ah[mi], &bb[ni >> 1][(ni & 1) * 2]);
        }
    }

    // epilogue
    #pragma unroll
    for (int mi = 0; mi < 4; mi++) {
        int row0 = bm + wm + mi * 16 + lr;
        #pragma unroll
        for (int ni = 0; ni < 8; ni++) {
            int col0 = bn + wn + ni * 8 + (lc << 1);
            float b0 = bias[col0], b1 = bias[col0 + 1];
            #pragma unroll
            for (int half = 0; half < 2; half++) {
                int row = row0 + half * 8;
                float v0 = acc[mi][ni][half * 2 + 0] + b0;
                float v1 = acc[mi][ni][half * 2 + 1] + b1;
                if (GELU_) {
                    v0 = 0.5f * v0 * (1.0f + erff(v0 * 0.70710678118654752f));
                    v1 = 0.5f * v1 * (1.0f + erff(v1 * 0.70710678118654752f));
                }
                if (RES_) {
                    float2 r2 = *(const float2*)(R + (size_t)row * N + col0);
                    v0 += r2.x; v1 += r2.y;
                }
                size_t off = (size_t)row * N + col0;
                if (OUTM_ == 2) {
                    *(uint32_t*)(Ch + off) = pack2h(v0, v1);
                } else {
                    *(float2*)(C + off) = make_float2(v0, v1);
                }
            }
        }
    }
}

// ---------------------------------------------------------------------------
// Fused flash attention (unchanged from R13).
// ---------------------------------------------------------------------------
#define FST    36
#define FARR   (64*FST)
#define FSTAGE (2*FARR*4)          // 18432
#define FSMEM  (3*FSTAGE)          // 55296
#define NTT    ((CS + 63) / 64)    // 13
#define NQB    ((CS + 127) / 128)  // 7

__global__ void __launch_bounds__(256, 2) flash_attn(
    const __half* __restrict__ qkv, __half* __restrict__ ctxh)
{
    extern __shared__ uint32_t fs[];
    int tid = threadIdx.x, lane = tid & 31, w = tid >> 5;
    int lr = lane >> 2, lc = lane & 3;
    int bh = blockIdx.y, b = bh / CH, h = bh % CH;
    int s0 = blockIdx.x * 128;
    uint32_t sb = smem_u32(fs);
    const float L2E = 1.4426950408889634f;

    uint32_t qf[4][4];
    {
        int r0 = min(s0 + w * 16 + lr, CS - 1);
        int r1 = min(s0 + w * 16 + lr + 8, CS - 1);
        const __half* q0 = qkv + ((size_t)b * CS + r0) * QKVD + h * CHD + 2 * lc;
        const __half* q1 = qkv + ((size_t)b * CS + r1) * QKVD + h * CHD + 2 * lc;
        #pragma unroll
        for (int kf = 0; kf < 4; kf++) {
            qf[kf][0] = *(const uint32_t*)(q0 + kf * 16);
            qf[kf][1] = *(const uint32_t*)(q1 + kf * 16);
            qf[kf][2] = *(const uint32_t*)(q0 + kf * 16 + 8);
            qf[kf][3] = *(const uint32_t*)(q1 + kf * 16 + 8);
        }
    }

    auto fill = [&](int tt, int st) {
        int t0 = tt * 64;
        uint32_t base = sb + st * FSTAGE;
        #pragma unroll
        for (int i = 0; i < 4; i++) {
            int idx = tid + 256 * i;
            int arr = idx >> 9;
            int c = idx & 511;
            int row = c >> 3, ch = c & 7;
            int t = min(t0 + row, CS - 1);
            const __half* src = qkv + ((size_t)b * CS + t) * QKVD
                              + (arr == 0 ? CD : 2 * CD) + h * CHD + ch * 8;
            uint32_t dst = base + arr * (FARR * 4) + row * (FST * 4) + ch * 16;
            CP16(dst, src);
        }
        asm volatile("cp.async.commit_group;" ::: "memory");
    };

    float m0 = -1e30f, m1 = -1e30f, l0 = 0.0f, l1 = 0.0f;
    float o[8][4];
    #pragma unroll
    for (int nj = 0; nj < 8; nj++)
        #pragma unroll
        for (int e = 0; e < 4; e++) o[nj][e] = 0.0f;

    fill(0, 0);
    fill(1, 1);

    for (int tt = 0; tt < NTT; tt++) {
        int st = tt % 3;
        asm volatile("cp.async.wait_group 1;" ::: "memory");
        __syncthreads();

        const uint32_t* KH = fs + st * (FSTAGE / 4);
        const uint32_t  VB = sb + st * FSTAGE + FARR * 4;

        if (tt + 2 < NTT) fill(tt + 2, (tt + 2) % 3);
        else asm volatile("cp.async.commit_group;" ::: "memory");

        float s[8][4];
        #pragma unroll
        for (int nj = 0; nj < 8; nj++) {
            s[nj][0] = s[nj][1] = s[nj][2] = s[nj][3] = 0.0f;
            int cb = (nj * 8 + lr) * FST;
            #pragma unroll
            for (int kf = 0; kf < 4; kf++) {
                uint32_t bh_[2] = { KH[cb + kf * 8 + lc], KH[cb + kf * 8 + lc + 4] };
                mma16f(s[nj], qf[kf], bh_);
            }
        }

        bool last = (tt == NTT - 1);
        #pragma unroll
        for (int nj = 0; nj < 8; nj++) {
            if (last && nj >= 2) {
                s[nj][0] = s[nj][1] = s[nj][2] = s[nj][3] = -1e30f;
            } else {
                s[nj][0] *= 0.125f; s[nj][1] *= 0.125f;
                s[nj][2] *= 0.125f; s[nj][3] *= 0.125f;
            }
        }

        float tm0 = -1e30f, tm1 = -1e30f;
        #pragma unroll
        for (int nj = 0; nj < 8; nj++) {
            tm0 = fmaxf(tm0, fmaxf(s[nj][0], s[nj][1]));
            tm1 = fmaxf(tm1, fmaxf(s[nj][2], s[nj][3]));
        }
        tm0 = fmaxf(tm0, __shfl_xor_sync(0xffffffffu, tm0, 1));
        tm0 = fmaxf(tm0, __shfl_xor_sync(0xffffffffu, tm0, 2));
        tm1 = fmaxf(tm1, __shfl_xor_sync(0xffffffffu, tm1, 1));
        tm1 = fmaxf(tm1, __shfl_xor_sync(0xffffffffu, tm1, 2));
        float mn0 = fmaxf(m0, tm0), mn1 = fmaxf(m1, tm1);
        float a0 = __expf(m0 - mn0), a1 = __expf(m1 - mn1);
        m0 = mn0; m1 = mn1;

        uint32_t ph[4][4];
        float rs0 = 0.0f, rs1 = 0.0f;
        #pragma unroll
        for (int kf = 0; kf < 4; kf++) {
            int nj0 = 2 * kf, nj1 = 2 * kf + 1;
            uint32_t u;
            u = pack2h((s[nj0][0] - mn0) * L2E, (s[nj0][1] - mn0) * L2E);
            EX2H2(ph[kf][0], u);
            u = pack2h((s[nj0][2] - mn1) * L2E, (s[nj0][3] - mn1) * L2E);
            EX2H2(ph[kf][1], u);
            u = pack2h((s[nj1][0] - mn0) * L2E, (s[nj1][1] - mn0) * L2E);
            EX2H2(ph[kf][2], u);
            u = pack2h((s[nj1][2] - mn1) * L2E, (s[nj1][3] - mn1) * L2E);
            EX2H2(ph[kf][3], u);
            float2 f;
            f = __half22float2(*(__half2*)&ph[kf][0]); rs0 += f.x + f.y;
            f = __half22float2(*(__half2*)&ph[kf][1]); rs1 += f.x + f.y;
            f = __half22float2(*(__half2*)&ph[kf][2]); rs0 += f.x + f.y;
            f = __half22float2(*(__half2*)&ph[kf][3]); rs1 += f.x + f.y;
        }
        rs0 += __shfl_xor_sync(0xffffffffu, rs0, 1);
        rs0 += __shfl_xor_sync(0xffffffffu, rs0, 2);
        rs1 += __shfl_xor_sync(0xffffffffu, rs1, 1);
        rs1 += __shfl_xor_sync(0xffffffffu, rs1, 2);
        l0 = l0 * a0 + rs0;
        l1 = l1 * a1 + rs1;

        #pragma unroll
        for (int nj = 0; nj < 8; nj++) {
            o[nj][0] *= a0; o[nj][1] *= a0;
            o[nj][2] *= a1; o[nj][3] *= a1;
        }

        #pragma unroll
        for (int kf = 0; kf < 4; kf++) {
            uint32_t vr[4][4];
            uint32_t rowa = VB + (kf * 16 + (lane & 15)) * 144 + (lane >> 4) * 16;
            #pragma unroll
            for (int njp = 0; njp < 4; njp++)
                LDMX4T(vr[njp], rowa + njp * 32);
            #pragma unroll
            for (int njp = 0; njp < 4; njp++) {
                mma16f(o[2 * njp],     ph[kf], &vr[njp][0]);
                mma16f(o[2 * njp + 1], ph[kf], &vr[njp][2]);
            }
        }
    }

    float i0 = 1.0f / l0, i1 = 1.0f / l1;
    int r0 = s0 + w * 16 + lr, r1 = r0 + 8;
    #pragma unroll
    for (int nj = 0; nj < 8; nj++) {
        int col = h * CHD + nj * 8 + 2 * lc;
        if (r0 < CS) {
            size_t off = ((size_t)b * CS + r0) * CD + col;
            *(uint32_t*)(ctxh + off) = pack2h(o[nj][0] * i0, o[nj][1] * i0);
        }
        if (r1 < CS) {
            size_t off = ((size_t)b * CS + r1) * CD + col;
            *(uint32_t*)(ctxh + off) = pack2h(o[nj][2] * i1, o[nj][3] * i1);
        }
    }
}

// ---------------------------------------------------------------------------
// Orchestration
// ---------------------------------------------------------------------------
extern "C" void kernel_launch(void* const* d_in, const int* in_sizes, int n_in,
                              void* d_out, int out_size)
{
    (void)in_sizes; (void)n_in; (void)out_size;

    const float* x     = (const float*)d_in[0];
    const float* ln1_s = (const float*)d_in[1];
    const float* ln1_b = (const float*)d_in[2];
    const float* wq    = (const float*)d_in[3];
    const float* bq    = (const float*)d_in[4];
    const float* wk    = (const float*)d_in[5];
    const float* bk    = (const float*)d_in[6];
    const float* wv    = (const float*)d_in[7];
    const float* bv    = (const float*)d_in[8];
    const float* wo    = (const float*)d_in[9];
    const float* bo    = (const float*)d_in[10];
    const float* ln2_s = (const float*)d_in[11];
    const float* ln2_b = (const float*)d_in[12];
    const float* w1    = (const float*)d_in[13];
    const float* b1    = (const float*)d_in[14];
    const float* w2    = (const float*)d_in[15];
    const float* b2    = (const float*)d_in[16];
    const float* lnf_s = (const float*)d_in[17];
    const float* lnf_b = (const float*)d_in[18];

    float *h, *bqkv;
    cudaGetSymbolAddress((void**)&h,    g_h);
    cudaGetSymbolAddress((void**)&bqkv, g_bqkv);

    __half *yh, *qkv, *ctxh, *mlph;
    cudaGetSymbolAddress((void**)&yh,   g_yh);
    cudaGetSymbolAddress((void**)&qkv,  g_qkv);
    cudaGetSymbolAddress((void**)&ctxh, g_ctxh);
    cudaGetSymbolAddress((void**)&mlph, g_mlph);

    __half *wqkvt, *wot, *w1t, *w2t;
    cudaGetSymbolAddress((void**)&wqkvt, g_wqkvt);
    cudaGetSymbolAddress((void**)&wot,  g_wot);
    cudaGetSymbolAddress((void**)&w1t,  g_w1t);
    cudaGetSymbolAddress((void**)&w2t,  g_w2t);

    cudaFuncSetAttribute(gemm_fp16<0,0,0>, cudaFuncAttributeMaxDynamicSharedMemorySize, GSMEM3);
    cudaFuncSetAttribute(gemm_fp16<0,0,2>, cudaFuncAttributeMaxDynamicSharedMemorySize, GSMEM3);
    cudaFuncSetAttribute(gemm_fp16<0,1,0>, cudaFuncAttributeMaxDynamicSharedMemorySize, GSMEM3);
    cudaFuncSetAttribute(gemm_fp16<1,0,2>, cudaFuncAttributeMaxDynamicSharedMemorySize, GSMEM3);
    cudaFuncSetAttribute(flash_attn, cudaFuncAttributeMaxDynamicSharedMemorySize, FSMEM);

    dim3 blk(256), blk128(128);

    prep_kernel<<<dim3(3456, CL), blk>>>(wq, wk, wv, wo, w1, w2,
                                         wqkvt, wot, w1t, w2t);
    pack_bias_kernel<<<CL, blk>>>(bq, bk, bv, bqkv);

    cudaMemcpyAsync(h, x, (size_t)CBS * CD * sizeof(float),
                    cudaMemcpyDeviceToDevice);

    dim3 gqkv(QKVD / 128, CBS / 128);   // (18, 49)
    dim3 gp768(CD / 128, CBS / 128);    // (6, 49)
    dim3 gp3072(CF / 128, CBS / 128);   // (24, 49)
    dim3 gfa(NQB, CB * CH);             // (7, 96)

    for (int l = 0; l < CL; l++) {
        size_t woQ   = (size_t)l * QKVD * CD;
        size_t wo768 = (size_t)l * CD * CD;
        size_t woF   = (size_t)l * CD * CF;
        ln_h_kernel<<<CBS, blk>>>(h, yh, ln1_s + l * CD, ln1_b + l * CD);
        gemm_fp16<0,0,2><<<gqkv, blk128, GSMEM3>>>(
            yh, wqkvt + woQ, bqkv + l * QKVD, nullptr, nullptr, qkv, QKVD, CD);
        flash_attn<<<gfa, blk, FSMEM>>>(qkv, ctxh);
        gemm_fp16<0,1,0><<<gp768, blk128, GSMEM3>>>(
            ctxh, wot + wo768, bo + l * CD, h, h, nullptr, CD, CD);
        ln_h_kernel<<<CBS, blk>>>(h, yh, ln2_s + l * CD, ln2_b + l * CD);
        gemm_fp16<1,0,2><<<gp3072, blk128, GSMEM3>>>(
            yh, w1t + woF, b1 + l * CF, nullptr, nullptr, mlph, CF, CD);
        gemm_fp16<0,1,0><<<gp768, blk128, GSMEM3>>>(
            mlph, w2t + woF, b2 + l * CD, h, h, nullptr, CD, CF);
    }
    ln_kernel<<<CBS, blk>>>(h, (float*)d_out, lnf_s, lnf_b);
}

// round 16
// speedup vs baseline: 1.0379x; 1.0379x over previous
#include <cuda_runtime.h>
#include <cuda_fp16.h>
#include <math.h>
#include <stdint.h>

// Problem constants
#define CL   12
#define CD   768
#define CH   12
#define CF   3072
#define CB   8
#define CS   784
#define CHD  64
#define CBS  (CB*CS)          // 6272 rows
#define CEPS 1e-6f
#define QKVD 2304             // packed q|k|v row width

// ---------------------------------------------------------------------------
// Scratch (device globals; no allocations allowed)
// ---------------------------------------------------------------------------
__device__ float g_h [CBS*CD];

__device__ __half g_yh  [CBS*CD];
__device__ __half g_qkv [(size_t)CBS*QKVD];
__device__ __half g_ctxh[CBS*CD];
__device__ __half g_mlph[(size_t)CBS*CF];

// transposed fp16 weights: qkv packed [L][2304][768]; others [L][N][K]
__device__ __half g_wqkvt[(size_t)CL*QKVD*CD];
__device__ __half g_wot[CL*CD*CD];
__device__ __half g_w1t[(size_t)CL*CD*CF];
__device__ __half g_w2t[(size_t)CL*CD*CF];
__device__ float  g_bqkv[CL*QKVD];

// ---------------------------------------------------------------------------
// helpers
// ---------------------------------------------------------------------------
__device__ __forceinline__ uint32_t smem_u32(const void* p) {
    return (uint32_t)__cvta_generic_to_shared(p);
}
__device__ __forceinline__ uint32_t pack2h(float a, float b) {
    __half2 t = __floats2half2_rn(a, b);
    return *reinterpret_cast<uint32_t*>(&t);
}

__device__ __forceinline__ void mma16f(float* c, const uint32_t* a, const uint32_t* b) {
    asm("mma.sync.aligned.m16n8k16.row.col.f32.f16.f16.f32 "
        "{%0,%1,%2,%3},{%4,%5,%6,%7},{%8,%9},{%0,%1,%2,%3};"
        : "+f"(c[0]), "+f"(c[1]), "+f"(c[2]), "+f"(c[3])
        : "r"(a[0]), "r"(a[1]), "r"(a[2]), "r"(a[3]), "r"(b[0]), "r"(b[1]));
}

#define CP16(dst, src) \
    asm volatile("cp.async.cg.shared.global [%0], [%1], 16;" \
                 :: "r"(dst), "l"(src) : "memory")

#define LDMX4(r, addr) \
    asm volatile("ldmatrix.sync.aligned.m8n8.x4.shared.b16 {%0,%1,%2,%3}, [%4];" \
                 : "=r"((r)[0]), "=r"((r)[1]), "=r"((r)[2]), "=r"((r)[3]) \
                 : "r"(addr))

#define LDMX4T(r, addr) \
    asm volatile("ldmatrix.sync.aligned.m8n8.x4.trans.shared.b16 {%0,%1,%2,%3}, [%4];" \
                 : "=r"((r)[0]), "=r"((r)[1]), "=r"((r)[2]), "=r"((r)[3]) \
                 : "r"(addr))

#define EX2H2(out, in) \
    asm("ex2.approx.f16x2 %0, %1;" : "=r"(out) : "r"(in))

// ---------------------------------------------------------------------------
// Block reduction (256 threads)
// ---------------------------------------------------------------------------
__device__ __forceinline__ float bsum(float v) {
    __shared__ float red[32];
    #pragma unroll
    for (int o = 16; o; o >>= 1) v += __shfl_xor_sync(0xffffffffu, v, o);
    if ((threadIdx.x & 31) == 0) red[threadIdx.x >> 5] = v;
    __syncthreads();
    float t = (threadIdx.x < (blockDim.x >> 5)) ? red[threadIdx.x] : 0.0f;
    if (threadIdx.x < 32) {
        #pragma unroll
        for (int o = 16; o; o >>= 1) t += __shfl_xor_sync(0xffffffffu, t, o);
        if (threadIdx.x == 0) red[0] = t;
    }
    __syncthreads();
    float r = red[0];
    __syncthreads();
    return r;
}

// ---------------------------------------------------------------------------
// Merged weight prep (unchanged from R13)
// ---------------------------------------------------------------------------
__global__ void __launch_bounds__(256) prep_kernel(
    const float* __restrict__ wq, const float* __restrict__ wk,
    const float* __restrict__ wv, const float* __restrict__ wo,
    const float* __restrict__ w1, const float* __restrict__ w2,
    __half* __restrict__ wqkvt, __half* __restrict__ wot,
    __half* __restrict__ w1t,   __half* __restrict__ w2t)
{
    __shared__ float t[64][33];
    int l = blockIdx.y, tile = blockIdx.x;
    const float* W;
    __half* T;
    int K, N, n0, k0;

    if (tile < 1152) {
        int seg = tile / 288, tt = tile % 288;
        K = CD; N = CD;
        n0 = (tt % 24) * 32; k0 = (tt / 24) * 64;
        if (seg < 3) {
            W = (seg == 0) ? wq : (seg == 1) ? wk : wv;
            W += (size_t)l * CD * CD;
            T = wqkvt + (size_t)l * QKVD * CD + (size_t)(seg * CD + n0) * CD + k0;
        } else {
            W = wo + (size_t)l * CD * CD;
            T = wot + (size_t)l * CD * CD + (size_t)n0 * CD + k0;
        }
    } else if (tile < 2304) {
        int tt = tile - 1152;
        K = CD; N = CF;
        n0 = (tt % 96) * 32; k0 = (tt / 96) * 64;
        W = w1 + (size_t)l * CD * CF;
        T = w1t + (size_t)l * CD * CF + (size_t)n0 * CD + k0;
    } else {
        int tt = tile - 2304;
        K = CF; N = CD;
        n0 = (tt % 24) * 32; k0 = (tt / 24) * 64;
        W = w2 + (size_t)l * CD * CF;
        T = w2t + (size_t)l * CD * CF + (size_t)n0 * CF + k0;
    }

    int tid = threadIdx.x, lane = tid & 31, w = tid >> 5;
    #pragma unroll
    for (int i = 0; i < 2; i++) {
        int idx = tid + 256 * i;
        int row = idx >> 3;
        int c4  = (idx & 7) << 2;
        float4 v = *(const float4*)(W + (size_t)(k0 + row) * N + n0 + c4);
        t[row][c4 + 0] = v.x; t[row][c4 + 1] = v.y;
        t[row][c4 + 2] = v.z; t[row][c4 + 3] = v.w;
    }
    __syncthreads();
    #pragma unroll
    for (int pass = 0; pass < 4; pass++) {
        int n = w + pass * 8;
        uint32_t p = pack2h(t[2 * lane][n], t[2 * lane + 1][n]);
        *(uint32_t*)(T + (size_t)n * K + 2 * lane) = p;
    }
}

// pack qkv biases: [L][2304] = bq | bk | bv
__global__ void __launch_bounds__(256) pack_bias_kernel(
    const float* __restrict__ bq, const float* __restrict__ bk,
    const float* __restrict__ bv, float* __restrict__ out)
{
    int l = blockIdx.x;
    for (int i = threadIdx.x; i < QKVD; i += 256) {
        float v = (i < CD) ? bq[l * CD + i]
                : (i < 2 * CD) ? bk[l * CD + i - CD]
                : bv[l * CD + i - 2 * CD];
        out[l * QKVD + i] = v;
    }
}

// ---------------------------------------------------------------------------
// LayerNorm -> fp32 out (final) — vectorized
// ---------------------------------------------------------------------------
__global__ void __launch_bounds__(256) ln_kernel(
    const float* __restrict__ in, float* __restrict__ out,
    const float* __restrict__ gs, const float* __restrict__ gb)
{
    int tid = threadIdx.x;
    const float4* x4 = (const float4*)(in + (size_t)blockIdx.x * CD);
    float4 v = make_float4(0.f, 0.f, 0.f, 0.f);
    if (tid < 192) v = x4[tid];
    float mean = bsum(v.x + v.y + v.z + v.w) * (1.0f / CD);
    float c0 = v.x - mean, c1 = v.y - mean, c2 = v.z - mean, c3 = v.w - mean;
    float sq = (tid < 192) ? (c0*c0 + c1*c1 + c2*c2 + c3*c3) : 0.0f;
    float var = bsum(sq) * (1.0f / CD);
    float r = rsqrtf(var + CEPS);
    if (tid < 192) {
        float4 g4 = ((const float4*)gs)[tid];
        float4 b4 = ((const float4*)gb)[tid];
        float4 o4 = make_float4(c0 * r * g4.x + b4.x, c1 * r * g4.y + b4.y,
                                c2 * r * g4.z + b4.z, c3 * r * g4.w + b4.w);
        ((float4*)(out + (size_t)blockIdx.x * CD))[tid] = o4;
    }
}

// LayerNorm -> fp16 — vectorized
__global__ void __launch_bounds__(256) ln_h_kernel(
    const float* __restrict__ in, __half* __restrict__ oh,
    const float* __restrict__ gs, const float* __restrict__ gb)
{
    int tid = threadIdx.x;
    const float4* x4 = (const float4*)(in + (size_t)blockIdx.x * CD);
    float4 v = make_float4(0.f, 0.f, 0.f, 0.f);
    if (tid < 192) v = x4[tid];
    float mean = bsum(v.x + v.y + v.z + v.w) * (1.0f / CD);
    float c0 = v.x - mean, c1 = v.y - mean, c2 = v.z - mean, c3 = v.w - mean;
    float sq = (tid < 192) ? (c0*c0 + c1*c1 + c2*c2 + c3*c3) : 0.0f;
    float var = bsum(sq) * (1.0f / CD);
    float r = rsqrtf(var + CEPS);
    if (tid < 192) {
        float4 g4 = ((const float4*)gs)[tid];
        float4 b4 = ((const float4*)gb)[tid];
        uint2 o2;
        o2.x = pack2h(c0 * r * g4.x + b4.x, c1 * r * g4.y + b4.y);
        o2.y = pack2h(c2 * r * g4.z + b4.z, c3 * r * g4.w + b4.w);
        ((uint2*)(oh + (size_t)blockIdx.x * CD))[tid] = o2;
    }
}

// ---------------------------------------------------------------------------
// fp16 GEMM (R13 config restored): C = A @ B^T (+bias/gelu/res).
// 128x128 CTA tile, KT=64, 8 warps (warp tile 64x32), 3-stage cp.async,
// 2 CTAs/SM. Only change vs R13: fill() issued right after the stage
// barrier so cp.async overlaps the MMA burst.
// OUTM_: 0 = fp32 C, 2 = fp16 Ch
// ---------------------------------------------------------------------------
#define GST    36864
#define GSMEM3 (3*GST)

template<int GELU_, int RES_, int OUTM_>
__global__ void __launch_bounds__(256, 2) gemm_fp16(
    const __half* __restrict__ Ah, const __half* __restrict__ Bh,
    const float* __restrict__ bias, const float* __restrict__ R,
    float* __restrict__ C, __half* __restrict__ Ch,
    int N, int K)
{
    extern __shared__ char smem[];
    const int tid = threadIdx.x, lane = tid & 31, wid = tid >> 5;
    const int bm = blockIdx.y * 128, bn = blockIdx.x * 128;
    const int wm = (wid >> 2) * 64, wn = (wid & 3) * 32;
    const int lr = lane >> 2, lc = lane & 3;
    const uint32_t sb = smem_u32(smem);

    const uint32_t a_off = (uint32_t)((wm + (lane & 15)) * 144 + (lane >> 4) * 16);
    const uint32_t b_off = (uint32_t)(18432 +
        (wn + ((lane >> 4) & 1) * 8 + (lane & 7)) * 144 + ((lane >> 3) & 1) * 16);

    auto fill = [&](int kt, int s) {
        int k0 = kt << 6;
        uint32_t stg = sb + s * GST;
        #pragma unroll
        for (int i = 0; i < 8; i++) {
            int idx = tid + 256 * i;
            int arr = idx >> 10;
            int c = idx & 1023;
            int row = c >> 3, ch = c & 7;
            const __half* g = (arr == 0) ? Ah : Bh;
            int rb = (arr == 0) ? bm : bn;
            const __half* src = g + (size_t)(rb + row) * K + k0 + ch * 8;
            uint32_t dst = stg + arr * 18432 + row * 144 + ch * 16;
            CP16(dst, src);
        }
        asm volatile("cp.async.commit_group;" ::: "memory");
    };

    float acc[4][4][4];
    #pragma unroll
    for (int mi = 0; mi < 4; mi++)
        #pragma unroll
        for (int ni = 0; ni < 4; ni++)
            #pragma unroll
            for (int e = 0; e < 4; e++) acc[mi][ni][e] = 0.0f;

    int NT = K >> 6;
    fill(0, 0);
    fill(1, 1);

    for (int kt = 0; kt < NT; kt++) {
        int s = kt % 3;
        asm volatile("cp.async.wait_group 1;" ::: "memory");
        __syncthreads();
        uint32_t stg = sb + s * GST;

        // issue next-tile loads first so LSU work overlaps the MMA burst
        if (kt + 2 < NT) fill(kt + 2, (kt + 2) % 3);
        else asm volatile("cp.async.commit_group;" ::: "memory");

        #pragma unroll
        for (int ks = 0; ks < 4; ks++) {
            uint32_t kb = ks * 32;
            uint32_t ah[4][4], bb[2][4];
            #pragma unroll
            for (int mi = 0; mi < 4; mi++)
                LDMX4(ah[mi], stg + a_off + mi * (16 * 144) + kb);
            #pragma unroll
            for (int nj = 0; nj < 2; nj++)
                LDMX4(bb[nj], stg + b_off + nj * (16 * 144) + kb);
            #pragma unroll
            for (int mi = 0; mi < 4; mi++)
                #pragma unroll
                for (int ni = 0; ni < 4; ni++)
                    mma16f(acc[mi][ni], ah[mi], &bb[ni >> 1][(ni & 1) * 2]);
        }
    }

    #pragma unroll
    for (int mi = 0; mi < 4; mi++) {
        int row0 = bm + wm + mi * 16 + lr;
        #pragma unroll
        for (int ni = 0; ni < 4; ni++) {
            int col0 = bn + wn + ni * 8 + (lc << 1);
            float b0 = bias[col0], b1 = bias[col0 + 1];
            #pragma unroll
            for (int half = 0; half < 2; half++) {
                int row = row0 + half * 8;
                float v0 = acc[mi][ni][half * 2 + 0] + b0;
                float v1 = acc[mi][ni][half * 2 + 1] + b1;
                if (GELU_) {
                    v0 = 0.5f * v0 * (1.0f + erff(v0 * 0.70710678118654752f));
                    v1 = 0.5f * v1 * (1.0f + erff(v1 * 0.70710678118654752f));
                }
                if (RES_) {
                    float2 r2 = *(const float2*)(R + (size_t)row * N + col0);
                    v0 += r2.x; v1 += r2.y;
                }
                size_t off = (size_t)row * N + col0;
                if (OUTM_ == 2) {
                    *(uint32_t*)(Ch + off) = pack2h(v0, v1);
                } else {
                    *(float2*)(C + off) = make_float2(v0, v1);
                }
            }
        }
    }
}

// ---------------------------------------------------------------------------
// Fused flash attention (exact R13 state).
// ---------------------------------------------------------------------------
#define FST    36
#define FARR   (64*FST)
#define FSTAGE (2*FARR*4)          // 18432
#define FSMEM  (3*FSTAGE)          // 55296
#define NTT    ((CS + 63) / 64)    // 13
#define NQB    ((CS + 127) / 128)  // 7

__global__ void __launch_bounds__(256, 2) flash_attn(
    const __half* __restrict__ qkv, __half* __restrict__ ctxh)
{
    extern __shared__ uint32_t fs[];
    int tid = threadIdx.x, lane = tid & 31, w = tid >> 5;
    int lr = lane >> 2, lc = lane & 3;
    int bh = blockIdx.y, b = bh / CH, h = bh % CH;
    int s0 = blockIdx.x * 128;
    uint32_t sb = smem_u32(fs);
    const float L2E = 1.4426950408889634f;

    uint32_t qf[4][4];
    {
        int r0 = min(s0 + w * 16 + lr, CS - 1);
        int r1 = min(s0 + w * 16 + lr + 8, CS - 1);
        const __half* q0 = qkv + ((size_t)b * CS + r0) * QKVD + h * CHD + 2 * lc;
        const __half* q1 = qkv + ((size_t)b * CS + r1) * QKVD + h * CHD + 2 * lc;
        #pragma unroll
        for (int kf = 0; kf < 4; kf++) {
            qf[kf][0] = *(const uint32_t*)(q0 + kf * 16);
            qf[kf][1] = *(const uint32_t*)(q1 + kf * 16);
            qf[kf][2] = *(const uint32_t*)(q0 + kf * 16 + 8);
            qf[kf][3] = *(const uint32_t*)(q1 + kf * 16 + 8);
        }
    }

    auto fill = [&](int tt, int st) {
        int t0 = tt * 64;
        uint32_t base = sb + st * FSTAGE;
        #pragma unroll
        for (int i = 0; i < 4; i++) {
            int idx = tid + 256 * i;
            int arr = idx >> 9;
            int c = idx & 511;
            int row = c >> 3, ch = c & 7;
            int t = min(t0 + row, CS - 1);
            const __half* src = qkv + ((size_t)b * CS + t) * QKVD
                              + (arr == 0 ? CD : 2 * CD) + h * CHD + ch * 8;
            uint32_t dst = base + arr * (FARR * 4) + row * (FST * 4) + ch * 16;
            CP16(dst, src);
        }
        asm volatile("cp.async.commit_group;" ::: "memory");
    };

    float m0 = -1e30f, m1 = -1e30f, l0 = 0.0f, l1 = 0.0f;
    float o[8][4];
    #pragma unroll
    for (int nj = 0; nj < 8; nj++)
        #pragma unroll
        for (int e = 0; e < 4; e++) o[nj][e] = 0.0f;

    fill(0, 0);
    fill(1, 1);

    for (int tt = 0; tt < NTT; tt++) {
        int st = tt % 3;
        asm volatile("cp.async.wait_group 1;" ::: "memory");
        __syncthreads();

        const uint32_t* KH = fs + st * (FSTAGE / 4);
        const uint32_t  VB = sb + st * FSTAGE + FARR * 4;

        float s[8][4];
        #pragma unroll
        for (int nj = 0; nj < 8; nj++) {
            s[nj][0] = s[nj][1] = s[nj][2] = s[nj][3] = 0.0f;
            int cb = (nj * 8 + lr) * FST;
            #pragma unroll
            for (int kf = 0; kf < 4; kf++) {
                uint32_t bh_[2] = { KH[cb + kf * 8 + lc], KH[cb + kf * 8 + lc + 4] };
                mma16f(s[nj], qf[kf], bh_);
            }
        }

        bool last = (tt == NTT - 1);
        #pragma unroll
        for (int nj = 0; nj < 8; nj++) {
            if (last && nj >= 2) {
                s[nj][0] = s[nj][1] = s[nj][2] = s[nj][3] = -1e30f;
            } else {
                s[nj][0] *= 0.125f; s[nj][1] *= 0.125f;
                s[nj][2] *= 0.125f; s[nj][3] *= 0.125f;
            }
        }

        float tm0 = -1e30f, tm1 = -1e30f;
        #pragma unroll
        for (int nj = 0; nj < 8; nj++) {
            tm0 = fmaxf(tm0, fmaxf(s[nj][0], s[nj][1]));
            tm1 = fmaxf(tm1, fmaxf(s[nj][2], s[nj][3]));
        }
        tm0 = fmaxf(tm0, __shfl_xor_sync(0xffffffffu, tm0, 1));
        tm0 = fmaxf(tm0, __shfl_xor_sync(0xffffffffu, tm0, 2));
        tm1 = fmaxf(tm1, __shfl_xor_sync(0xffffffffu, tm1, 1));
        tm1 = fmaxf(tm1, __shfl_xor_sync(0xffffffffu, tm1, 2));
        float mn0 = fmaxf(m0, tm0), mn1 = fmaxf(m1, tm1);
        float a0 = __expf(m0 - mn0), a1 = __expf(m1 - mn1);
        m0 = mn0; m1 = mn1;

        uint32_t ph[4][4];
        float rs0 = 0.0f, rs1 = 0.0f;
        #pragma unroll
        for (int kf = 0; kf < 4; kf++) {
            int nj0 = 2 * kf, nj1 = 2 * kf + 1;
            uint32_t u;
            u = pack2h((s[nj0][0] - mn0) * L2E, (s[nj0][1] - mn0) * L2E);
            EX2H2(ph[kf][0], u);
            u = pack2h((s[nj0][2] - mn1) * L2E, (s[nj0][3] - mn1) * L2E);
            EX2H2(ph[kf][1], u);
            u = pack2h((s[nj1][0] - mn0) * L2E, (s[nj1][1] - mn0) * L2E);
            EX2H2(ph[kf][2], u);
            u = pack2h((s[nj1][2] - mn1) * L2E, (s[nj1][3] - mn1) * L2E);
            EX2H2(ph[kf][3], u);
            float2 f;
            f = __half22float2(*(__half2*)&ph[kf][0]); rs0 += f.x + f.y;
            f = __half22float2(*(__half2*)&ph[kf][1]); rs1 += f.x + f.y;
            f = __half22float2(*(__half2*)&ph[kf][2]); rs0 += f.x + f.y;
            f = __half22float2(*(__half2*)&ph[kf][3]); rs1 += f.x + f.y;
        }
        rs0 += __shfl_xor_sync(0xffffffffu, rs0, 1);
        rs0 += __shfl_xor_sync(0xffffffffu, rs0, 2);
        rs1 += __shfl_xor_sync(0xffffffffu, rs1, 1);
        rs1 += __shfl_xor_sync(0xffffffffu, rs1, 2);
        l0 = l0 * a0 + rs0;
        l1 = l1 * a1 + rs1;

        #pragma unroll
        for (int nj = 0; nj < 8; nj++) {
            o[nj][0] *= a0; o[nj][1] *= a0;
            o[nj][2] *= a1; o[nj][3] *= a1;
        }

        #pragma unroll
        for (int kf = 0; kf < 4; kf++) {
            uint32_t vr[4][4];
            uint32_t rowa = VB + (kf * 16 + (lane & 15)) * 144 + (lane >> 4) * 16;
            #pragma unroll
            for (int njp = 0; njp < 4; njp++)
                LDMX4T(vr[njp], rowa + njp * 32);
            #pragma unroll
            for (int njp = 0; njp < 4; njp++) {
                mma16f(o[2 * njp],     ph[kf], &vr[njp][0]);
                mma16f(o[2 * njp + 1], ph[kf], &vr[njp][2]);
            }
        }

        if (tt + 2 < NTT) fill(tt + 2, (tt + 2) % 3);
        else asm volatile("cp.async.commit_group;" ::: "memory");
    }

    float i0 = 1.0f / l0, i1 = 1.0f / l1;
    int r0 = s0 + w * 16 + lr, r1 = r0 + 8;
    #pragma unroll
    for (int nj = 0; nj < 8; nj++) {
        int col = h * CHD + nj * 8 + 2 * lc;
        if (r0 < CS) {
            size_t off = ((size_t)b * CS + r0) * CD + col;
            *(uint32_t*)(ctxh + off) = pack2h(o[nj][0] * i0, o[nj][1] * i0);
        }
        if (r1 < CS) {
            size_t off = ((size_t)b * CS + r1) * CD + col;
            *(uint32_t*)(ctxh + off) = pack2h(o[nj][2] * i1, o[nj][3] * i1);
        }
    }
}

// ---------------------------------------------------------------------------
// Orchestration
// ---------------------------------------------------------------------------
extern "C" void kernel_launch(void* const* d_in, const int* in_sizes, int n_in,
                              void* d_out, int out_size)
{
    (void)in_sizes; (void)n_in; (void)out_size;

    const float* x     = (const float*)d_in[0];
    const float* ln1_s = (const float*)d_in[1];
    const float* ln1_b = (const float*)d_in[2];
    const float* wq    = (const float*)d_in[3];
    const float* bq    = (const float*)d_in[4];
    const float* wk    = (const float*)d_in[5];
    const float* bk    = (const float*)d_in[6];
    const float* wv    = (const float*)d_in[7];
    const float* bv    = (const float*)d_in[8];
    const float* wo    = (const float*)d_in[9];
    const float* bo    = (const float*)d_in[10];
    const float* ln2_s = (const float*)d_in[11];
    const float* ln2_b = (const float*)d_in[12];
    const float* w1    = (const float*)d_in[13];
    const float* b1    = (const float*)d_in[14];
    const float* w2    = (const float*)d_in[15];
    const float* b2    = (const float*)d_in[16];
    const float* lnf_s = (const float*)d_in[17];
    const float* lnf_b = (const float*)d_in[18];

    float *h, *bqkv;
    cudaGetSymbolAddress((void**)&h,    g_h);
    cudaGetSymbolAddress((void**)&bqkv, g_bqkv);

    __half *yh, *qkv, *ctxh, *mlph;
    cudaGetSymbolAddress((void**)&yh,   g_yh);
    cudaGetSymbolAddress((void**)&qkv,  g_qkv);
    cudaGetSymbolAddress((void**)&ctxh, g_ctxh);
    cudaGetSymbolAddress((void**)&mlph, g_mlph);

    __half *wqkvt, *wot, *w1t, *w2t;
    cudaGetSymbolAddress((void**)&wqkvt, g_wqkvt);
    cudaGetSymbolAddress((void**)&wot,  g_wot);
    cudaGetSymbolAddress((void**)&w1t,  g_w1t);
    cudaGetSymbolAddress((void**)&w2t,  g_w2t);

    cudaFuncSetAttribute(gemm_fp16<0,0,0>, cudaFuncAttributeMaxDynamicSharedMemorySize, GSMEM3);
    cudaFuncSetAttribute(gemm_fp16<0,0,2>, cudaFuncAttributeMaxDynamicSharedMemorySize, GSMEM3);
    cudaFuncSetAttribute(gemm_fp16<0,1,0>, cudaFuncAttributeMaxDynamicSharedMemorySize, GSMEM3);
    cudaFuncSetAttribute(gemm_fp16<1,0,2>, cudaFuncAttributeMaxDynamicSharedMemorySize, GSMEM3);
    cudaFuncSetAttribute(flash_attn, cudaFuncAttributeMaxDynamicSharedMemorySize, FSMEM);

    dim3 blk(256);

    prep_kernel<<<dim3(3456, CL), blk>>>(wq, wk, wv, wo, w1, w2,
                                         wqkvt, wot, w1t, w2t);
    pack_bias_kernel<<<CL, blk>>>(bq, bk, bv, bqkv);

    cudaMemcpyAsync(h, x, (size_t)CBS * CD * sizeof(float),
                    cudaMemcpyDeviceToDevice);

    dim3 gqkv(QKVD / 128, CBS / 128);   // (18, 49)
    dim3 gp768(CD / 128, CBS / 128);    // (6, 49)
    dim3 gp3072(CF / 128, CBS / 128);   // (24, 49)
    dim3 gfa(NQB, CB * CH);             // (7, 96)

    for (int l = 0; l < CL; l++) {
        size_t woQ   = (size_t)l * QKVD * CD;
        size_t wo768 = (size_t)l * CD * CD;
        size_t woF   = (size_t)l * CD * CF;
        ln_h_kernel<<<CBS, blk>>>(h, yh, ln1_s + l * CD, ln1_b + l * CD);
        gemm_fp16<0,0,2><<<gqkv, blk, GSMEM3>>>(
            yh, wqkvt + woQ, bqkv + l * QKVD, nullptr, nullptr, qkv, QKVD, CD);
        flash_attn<<<gfa, blk, FSMEM>>>(qkv, ctxh);
        gemm_fp16<0,1,0><<<gp768, blk, GSMEM3>>>(
            ctxh, wot + wo768, bo + l * CD, h, h, nullptr, CD, CD);
        ln_h_kernel<<<CBS, blk>>>(h, yh, ln2_s + l * CD, ln2_b + l * CD);
        gemm_fp16<1,0,2><<<gp3072, blk, GSMEM3>>>(
            yh, w1t + woF, b1 + l * CF, nullptr, nullptr, mlph, CF, CD);
        gemm_fp16<0,1,0><<<gp768, blk, GSMEM3>>>(
            mlph, w2t + woF, b2 + l * CD, h, h, nullptr, CD, CF);
    }
    ln_kernel<<<CBS, blk>>>(h, (float*)d_out, lnf_s, lnf_b);
}

// round 17
// speedup vs baseline: 1.1023x; 1.0620x over previous
#include <cuda_runtime.h>
#include <cuda_fp16.h>
#include <math.h>
#include <stdint.h>

// Problem constants
#define CL   12
#define CD   768
#define CH   12
#define CF   3072
#define CB   8
#define CS   784
#define CHD  64
#define CBS  (CB*CS)          // 6272 rows
#define CEPS 1e-6f
#define QKVD 2304             // packed q|k|v row width

// ---------------------------------------------------------------------------
// Scratch (device globals; no allocations allowed)
// ---------------------------------------------------------------------------
__device__ float g_h [CBS*CD];

__device__ __half g_yh  [CBS*CD];
__device__ __half g_qkv [(size_t)CBS*QKVD];
__device__ __half g_ctxh[CBS*CD];
__device__ __half g_mlph[(size_t)CBS*CF];

// transposed fp16 weights: qkv packed [L][2304][768]; others [L][N][K]
__device__ __half g_wqkvt[(size_t)CL*QKVD*CD];
__device__ __half g_wot[CL*CD*CD];
__device__ __half g_w1t[(size_t)CL*CD*CF];
__device__ __half g_w2t[(size_t)CL*CD*CF];
__device__ float  g_bqkv[CL*QKVD];

// ---------------------------------------------------------------------------
// helpers
// ---------------------------------------------------------------------------
__device__ __forceinline__ uint32_t smem_u32(const void* p) {
    return (uint32_t)__cvta_generic_to_shared(p);
}
__device__ __forceinline__ uint32_t pack2h(float a, float b) {
    __half2 t = __floats2half2_rn(a, b);
    return *reinterpret_cast<uint32_t*>(&t);
}

__device__ __forceinline__ void mma16f(float* c, const uint32_t* a, const uint32_t* b) {
    asm("mma.sync.aligned.m16n8k16.row.col.f32.f16.f16.f32 "
        "{%0,%1,%2,%3},{%4,%5,%6,%7},{%8,%9},{%0,%1,%2,%3};"
        : "+f"(c[0]), "+f"(c[1]), "+f"(c[2]), "+f"(c[3])
        : "r"(a[0]), "r"(a[1]), "r"(a[2]), "r"(a[3]), "r"(b[0]), "r"(b[1]));
}

#define CP16(dst, src) \
    asm volatile("cp.async.cg.shared.global [%0], [%1], 16;" \
                 :: "r"(dst), "l"(src) : "memory")

#define LDMX4(r, addr) \
    asm volatile("ldmatrix.sync.aligned.m8n8.x4.shared.b16 {%0,%1,%2,%3}, [%4];" \
                 : "=r"((r)[0]), "=r"((r)[1]), "=r"((r)[2]), "=r"((r)[3]) \
                 : "r"(addr))

#define LDMX4T(r, addr) \
    asm volatile("ldmatrix.sync.aligned.m8n8.x4.trans.shared.b16 {%0,%1,%2,%3}, [%4];" \
                 : "=r"((r)[0]), "=r"((r)[1]), "=r"((r)[2]), "=r"((r)[3]) \
                 : "r"(addr))

#define EX2H2(out, in) \
    asm("ex2.approx.f16x2 %0, %1;" : "=r"(out) : "r"(in))

// ---------------------------------------------------------------------------
// Block reduction (works for any blockDim multiple of 32)
// ---------------------------------------------------------------------------
__device__ __forceinline__ float bsum(float v) {
    __shared__ float red[32];
    #pragma unroll
    for (int o = 16; o; o >>= 1) v += __shfl_xor_sync(0xffffffffu, v, o);
    if ((threadIdx.x & 31) == 0) red[threadIdx.x >> 5] = v;
    __syncthreads();
    float t = (threadIdx.x < (blockDim.x >> 5)) ? red[threadIdx.x] : 0.0f;
    if (threadIdx.x < 32) {
        #pragma unroll
        for (int o = 16; o; o >>= 1) t += __shfl_xor_sync(0xffffffffu, t, o);
        if (threadIdx.x == 0) red[0] = t;
    }
    __syncthreads();
    float r = red[0];
    __syncthreads();
    return r;
}

// ---------------------------------------------------------------------------
// Merged weight prep + bias pack. grid = (3457 tiles, 12 layers).
// tiles [0,3456): weight transpose/convert as R13; tile 3456: bias pack.
// ---------------------------------------------------------------------------
__global__ void __launch_bounds__(256) prep_kernel(
    const float* __restrict__ wq, const float* __restrict__ wk,
    const float* __restrict__ wv, const float* __restrict__ wo,
    const float* __restrict__ w1, const float* __restrict__ w2,
    const float* __restrict__ bq, const float* __restrict__ bk,
    const float* __restrict__ bv,
    __half* __restrict__ wqkvt, __half* __restrict__ wot,
    __half* __restrict__ w1t,   __half* __restrict__ w2t,
    float* __restrict__ bqkv)
{
    __shared__ float t[64][33];
    int l = blockIdx.y, tile = blockIdx.x;

    if (tile == 3456) {      // bias pack for layer l
        for (int i = threadIdx.x; i < QKVD; i += 256) {
            float v = (i < CD) ? bq[l * CD + i]
                    : (i < 2 * CD) ? bk[l * CD + i - CD]
                    : bv[l * CD + i - 2 * CD];
            bqkv[l * QKVD + i] = v;
        }
        return;
    }

    const float* W;
    __half* T;
    int K, N, n0, k0;

    if (tile < 1152) {
        int seg = tile / 288, tt = tile % 288;
        K = CD; N = CD;
        n0 = (tt % 24) * 32; k0 = (tt / 24) * 64;
        if (seg < 3) {
            W = (seg == 0) ? wq : (seg == 1) ? wk : wv;
            W += (size_t)l * CD * CD;
            T = wqkvt + (size_t)l * QKVD * CD + (size_t)(seg * CD + n0) * CD + k0;
        } else {
            W = wo + (size_t)l * CD * CD;
            T = wot + (size_t)l * CD * CD + (size_t)n0 * CD + k0;
        }
    } else if (tile < 2304) {
        int tt = tile - 1152;
        K = CD; N = CF;
        n0 = (tt % 96) * 32; k0 = (tt / 96) * 64;
        W = w1 + (size_t)l * CD * CF;
        T = w1t + (size_t)l * CD * CF + (size_t)n0 * CD + k0;
    } else {
        int tt = tile - 2304;
        K = CF; N = CD;
        n0 = (tt % 24) * 32; k0 = (tt / 24) * 64;
        W = w2 + (size_t)l * CD * CF;
        T = w2t + (size_t)l * CD * CF + (size_t)n0 * CF + k0;
    }

    int tid = threadIdx.x, lane = tid & 31, w = tid >> 5;
    #pragma unroll
    for (int i = 0; i < 2; i++) {
        int idx = tid + 256 * i;
        int row = idx >> 3;
        int c4  = (idx & 7) << 2;
        float4 v = *(const float4*)(W + (size_t)(k0 + row) * N + n0 + c4);
        t[row][c4 + 0] = v.x; t[row][c4 + 1] = v.y;
        t[row][c4 + 2] = v.z; t[row][c4 + 3] = v.w;
    }
    __syncthreads();
    #pragma unroll
    for (int pass = 0; pass < 4; pass++) {
        int n = w + pass * 8;
        uint32_t p = pack2h(t[2 * lane][n], t[2 * lane + 1][n]);
        *(uint32_t*)(T + (size_t)n * K + 2 * lane) = p;
    }
}

// ---------------------------------------------------------------------------
// LayerNorm -> fp32 out (final) — 192 threads, all active
// ---------------------------------------------------------------------------
__global__ void __launch_bounds__(192) ln_kernel(
    const float* __restrict__ in, float* __restrict__ out,
    const float* __restrict__ gs, const float* __restrict__ gb)
{
    int tid = threadIdx.x;
    const float4* x4 = (const float4*)(in + (size_t)blockIdx.x * CD);
    float4 v = x4[tid];
    float mean = bsum(v.x + v.y + v.z + v.w) * (1.0f / CD);
    float c0 = v.x - mean, c1 = v.y - mean, c2 = v.z - mean, c3 = v.w - mean;
    float var = bsum(c0*c0 + c1*c1 + c2*c2 + c3*c3) * (1.0f / CD);
    float r = rsqrtf(var + CEPS);
    float4 g4 = ((const float4*)gs)[tid];
    float4 b4 = ((const float4*)gb)[tid];
    float4 o4 = make_float4(c0 * r * g4.x + b4.x, c1 * r * g4.y + b4.y,
                            c2 * r * g4.z + b4.z, c3 * r * g4.w + b4.w);
    ((float4*)(out + (size_t)blockIdx.x * CD))[tid] = o4;
}

// LayerNorm -> fp16 — 192 threads, all active
__global__ void __launch_bounds__(192) ln_h_kernel(
    const float* __restrict__ in, __half* __restrict__ oh,
    const float* __restrict__ gs, const float* __restrict__ gb)
{
    int tid = threadIdx.x;
    const float4* x4 = (const float4*)(in + (size_t)blockIdx.x * CD);
    float4 v = x4[tid];
    float mean = bsum(v.x + v.y + v.z + v.w) * (1.0f / CD);
    float c0 = v.x - mean, c1 = v.y - mean, c2 = v.z - mean, c3 = v.w - mean;
    float var = bsum(c0*c0 + c1*c1 + c2*c2 + c3*c3) * (1.0f / CD);
    float r = rsqrtf(var + CEPS);
    float4 g4 = ((const float4*)gs)[tid];
    float4 b4 = ((const float4*)gb)[tid];
    uint2 o2;
    o2.x = pack2h(c0 * r * g4.x + b4.x, c1 * r * g4.y + b4.y);
    o2.y = pack2h(c2 * r * g4.z + b4.z, c3 * r * g4.w + b4.w);
    ((uint2*)(oh + (size_t)blockIdx.x * CD))[tid] = o2;
}

// ---------------------------------------------------------------------------
// fp16 GEMM — EXACT R13 configuration (measured best: 68.9us on QKV).
// 128x128 CTA tile, KT=64, 8 warps (warp tile 64x32), 3-stage cp.async,
// 2 CTAs/SM, fill at loop tail.
// OUTM_: 0 = fp32 C, 2 = fp16 Ch
// ---------------------------------------------------------------------------
#define GST    36864
#define GSMEM3 (3*GST)

template<int GELU_, int RES_, int OUTM_>
__global__ void __launch_bounds__(256, 2) gemm_fp16(
    const __half* __restrict__ Ah, const __half* __restrict__ Bh,
    const float* __restrict__ bias, const float* __restrict__ R,
    float* __restrict__ C, __half* __restrict__ Ch,
    int N, int K)
{
    extern __shared__ char smem[];
    const int tid = threadIdx.x, lane = tid & 31, wid = tid >> 5;
    const int bm = blockIdx.y * 128, bn = blockIdx.x * 128;
    const int wm = (wid >> 2) * 64, wn = (wid & 3) * 32;
    const int lr = lane >> 2, lc = lane & 3;
    const uint32_t sb = smem_u32(smem);

    const uint32_t a_off = (uint32_t)((wm + (lane & 15)) * 144 + (lane >> 4) * 16);
    const uint32_t b_off = (uint32_t)(18432 +
        (wn + ((lane >> 4) & 1) * 8 + (lane & 7)) * 144 + ((lane >> 3) & 1) * 16);

    auto fill = [&](int kt, int s) {
        int k0 = kt << 6;
        uint32_t stg = sb + s * GST;
        #pragma unroll
        for (int i = 0; i < 8; i++) {
            int idx = tid + 256 * i;
            int arr = idx >> 10;
            int c = idx & 1023;
            int row = c >> 3, ch = c & 7;
            const __half* g = (arr == 0) ? Ah : Bh;
            int rb = (arr == 0) ? bm : bn;
            const __half* src = g + (size_t)(rb + row) * K + k0 + ch * 8;
            uint32_t dst = stg + arr * 18432 + row * 144 + ch * 16;
            CP16(dst, src);
        }
        asm volatile("cp.async.commit_group;" ::: "memory");
    };

    float acc[4][4][4];
    #pragma unroll
    for (int mi = 0; mi < 4; mi++)
        #pragma unroll
        for (int ni = 0; ni < 4; ni++)
            #pragma unroll
            for (int e = 0; e < 4; e++) acc[mi][ni][e] = 0.0f;

    int NT = K >> 6;
    fill(0, 0);
    fill(1, 1);

    for (int kt = 0; kt < NT; kt++) {
        int s = kt % 3;
        asm volatile("cp.async.wait_group 1;" ::: "memory");
        __syncthreads();
        uint32_t stg = sb + s * GST;

        #pragma unroll
        for (int ks = 0; ks < 4; ks++) {
            uint32_t kb = ks * 32;
            uint32_t ah[4][4], bb[2][4];
            #pragma unroll
            for (int mi = 0; mi < 4; mi++)
                LDMX4(ah[mi], stg + a_off + mi * (16 * 144) + kb);
            #pragma unroll
            for (int nj = 0; nj < 2; nj++)
                LDMX4(bb[nj], stg + b_off + nj * (16 * 144) + kb);
            #pragma unroll
            for (int mi = 0; mi < 4; mi++)
                #pragma unroll
                for (int ni = 0; ni < 4; ni++)
                    mma16f(acc[mi][ni], ah[mi], &bb[ni >> 1][(ni & 1) * 2]);
        }
        if (kt + 2 < NT) fill(kt + 2, (kt + 2) % 3);
        else asm volatile("cp.async.commit_group;" ::: "memory");
    }

    #pragma unroll
    for (int mi = 0; mi < 4; mi++) {
        int row0 = bm + wm + mi * 16 + lr;
        #pragma unroll
        for (int ni = 0; ni < 4; ni++) {
            int col0 = bn + wn + ni * 8 + (lc << 1);
            float b0 = bias[col0], b1 = bias[col0 + 1];
            #pragma unroll
            for (int half = 0; half < 2; half++) {
                int row = row0 + half * 8;
                float v0 = acc[mi][ni][half * 2 + 0] + b0;
                float v1 = acc[mi][ni][half * 2 + 1] + b1;
                if (GELU_) {
                    v0 = 0.5f * v0 * (1.0f + erff(v0 * 0.70710678118654752f));
                    v1 = 0.5f * v1 * (1.0f + erff(v1 * 0.70710678118654752f));
                }
                if (RES_) {
                    float2 r2 = *(const float2*)(R + (size_t)row * N + col0);
                    v0 += r2.x; v1 += r2.y;
                }
                size_t off = (size_t)row * N + col0;
                if (OUTM_ == 2) {
                    *(uint32_t*)(Ch + off) = pack2h(v0, v1);
                } else {
                    *(float2*)(C + off) = make_float2(v0, v1);
                }
            }
        }
    }
}

// ---------------------------------------------------------------------------
// Fused flash attention — EXACT R13 state.
// ---------------------------------------------------------------------------
#define FST    36
#define FARR   (64*FST)
#define FSTAGE (2*FARR*4)          // 18432
#define FSMEM  (3*FSTAGE)          // 55296
#define NTT    ((CS + 63) / 64)    // 13
#define NQB    ((CS + 127) / 128)  // 7

__global__ void __launch_bounds__(256, 2) flash_attn(
    const __half* __restrict__ qkv, __half* __restrict__ ctxh)
{
    extern __shared__ uint32_t fs[];
    int tid = threadIdx.x, lane = tid & 31, w = tid >> 5;
    int lr = lane >> 2, lc = lane & 3;
    int bh = blockIdx.y, b = bh / CH, h = bh % CH;
    int s0 = blockIdx.x * 128;
    uint32_t sb = smem_u32(fs);
    const float L2E = 1.4426950408889634f;

    uint32_t qf[4][4];
    {
        int r0 = min(s0 + w * 16 + lr, CS - 1);
        int r1 = min(s0 + w * 16 + lr + 8, CS - 1);
        const __half* q0 = qkv + ((size_t)b * CS + r0) * QKVD + h * CHD + 2 * lc;
        const __half* q1 = qkv + ((size_t)b * CS + r1) * QKVD + h * CHD + 2 * lc;
        #pragma unroll
        for (int kf = 0; kf < 4; kf++) {
            qf[kf][0] = *(const uint32_t*)(q0 + kf * 16);
            qf[kf][1] = *(const uint32_t*)(q1 + kf * 16);
            qf[kf][2] = *(const uint32_t*)(q0 + kf * 16 + 8);
            qf[kf][3] = *(const uint32_t*)(q1 + kf * 16 + 8);
        }
    }

    auto fill = [&](int tt, int st) {
        int t0 = tt * 64;
        uint32_t base = sb + st * FSTAGE;
        #pragma unroll
        for (int i = 0; i < 4; i++) {
            int idx = tid + 256 * i;
            int arr = idx >> 9;
            int c = idx & 511;
            int row = c >> 3, ch = c & 7;
            int t = min(t0 + row, CS - 1);
            const __half* src = qkv + ((size_t)b * CS + t) * QKVD
                              + (arr == 0 ? CD : 2 * CD) + h * CHD + ch * 8;
            uint32_t dst = base + arr * (FARR * 4) + row * (FST * 4) + ch * 16;
            CP16(dst, src);
        }
        asm volatile("cp.async.commit_group;" ::: "memory");
    };

    float m0 = -1e30f, m1 = -1e30f, l0 = 0.0f, l1 = 0.0f;
    float o[8][4];
    #pragma unroll
    for (int nj = 0; nj < 8; nj++)
        #pragma unroll
        for (int e = 0; e < 4; e++) o[nj][e] = 0.0f;

    fill(0, 0);
    fill(1, 1);

    for (int tt = 0; tt < NTT; tt++) {
        int st = tt % 3;
        asm volatile("cp.async.wait_group 1;" ::: "memory");
        __syncthreads();

        const uint32_t* KH = fs + st * (FSTAGE / 4);
        const uint32_t  VB = sb + st * FSTAGE + FARR * 4;

        float s[8][4];
        #pragma unroll
        for (int nj = 0; nj < 8; nj++) {
            s[nj][0] = s[nj][1] = s[nj][2] = s[nj][3] = 0.0f;
            int cb = (nj * 8 + lr) * FST;
            #pragma unroll
            for (int kf = 0; kf < 4; kf++) {
                uint32_t bh_[2] = { KH[cb + kf * 8 + lc], KH[cb + kf * 8 + lc + 4] };
                mma16f(s[nj], qf[kf], bh_);
            }
        }

        bool last = (tt == NTT - 1);
        #pragma unroll
        for (int nj = 0; nj < 8; nj++) {
            if (last && nj >= 2) {
                s[nj][0] = s[nj][1] = s[nj][2] = s[nj][3] = -1e30f;
            } else {
                s[nj][0] *= 0.125f; s[nj][1] *= 0.125f;
                s[nj][2] *= 0.125f; s[nj][3] *= 0.125f;
            }
        }

        float tm0 = -1e30f, tm1 = -1e30f;
        #pragma unroll
        for (int nj = 0; nj < 8; nj++) {
            tm0 = fmaxf(tm0, fmaxf(s[nj][0], s[nj][1]));
            tm1 = fmaxf(tm1, fmaxf(s[nj][2], s[nj][3]));
        }
        tm0 = fmaxf(tm0, __shfl_xor_sync(0xffffffffu, tm0, 1));
        tm0 = fmaxf(tm0, __shfl_xor_sync(0xffffffffu, tm0, 2));
        tm1 = fmaxf(tm1, __shfl_xor_sync(0xffffffffu, tm1, 1));
        tm1 = fmaxf(tm1, __shfl_xor_sync(0xffffffffu, tm1, 2));
        float mn0 = fmaxf(m0, tm0), mn1 = fmaxf(m1, tm1);
        float a0 = __expf(m0 - mn0), a1 = __expf(m1 - mn1);
        m0 = mn0; m1 = mn1;

        uint32_t ph[4][4];
        float rs0 = 0.0f, rs1 = 0.0f;
        #pragma unroll
        for (int kf = 0; kf < 4; kf++) {
            int nj0 = 2 * kf, nj1 = 2 * kf + 1;
            uint32_t u;
            u = pack2h((s[nj0][0] - mn0) * L2E, (s[nj0][1] - mn0) * L2E);
            EX2H2(ph[kf][0], u);
            u = pack2h((s[nj0][2] - mn1) * L2E, (s[nj0][3] - mn1) * L2E);
            EX2H2(ph[kf][1], u);
            u = pack2h((s[nj1][0] - mn0) * L2E, (s[nj1][1] - mn0) * L2E);
            EX2H2(ph[kf][2], u);
            u = pack2h((s[nj1][2] - mn1) * L2E, (s[nj1][3] - mn1) * L2E);
            EX2H2(ph[kf][3], u);
            float2 f;
            f = __half22float2(*(__half2*)&ph[kf][0]); rs0 += f.x + f.y;
            f = __half22float2(*(__half2*)&ph[kf][1]); rs1 += f.x + f.y;
            f = __half22float2(*(__half2*)&ph[kf][2]); rs0 += f.x + f.y;
            f = __half22float2(*(__half2*)&ph[kf][3]); rs1 += f.x + f.y;
        }
        rs0 += __shfl_xor_sync(0xffffffffu, rs0, 1);
        rs0 += __shfl_xor_sync(0xffffffffu, rs0, 2);
        rs1 += __shfl_xor_sync(0xffffffffu, rs1, 1);
        rs1 += __shfl_xor_sync(0xffffffffu, rs1, 2);
        l0 = l0 * a0 + rs0;
        l1 = l1 * a1 + rs1;

        #pragma unroll
        for (int nj = 0; nj < 8; nj++) {
            o[nj][0] *= a0; o[nj][1] *= a0;
            o[nj][2] *= a1; o[nj][3] *= a1;
        }

        #pragma unroll
        for (int kf = 0; kf < 4; kf++) {
            uint32_t vr[4][4];
            uint32_t rowa = VB + (kf * 16 + (lane & 15)) * 144 + (lane >> 4) * 16;
            #pragma unroll
            for (int njp = 0; njp < 4; njp++)
                LDMX4T(vr[njp], rowa + njp * 32);
            #pragma unroll
            for (int njp = 0; njp < 4; njp++) {
                mma16f(o[2 * njp],     ph[kf], &vr[njp][0]);
                mma16f(o[2 * njp + 1], ph[kf], &vr[njp][2]);
            }
        }

        if (tt + 2 < NTT) fill(tt + 2, (tt + 2) % 3);
        else asm volatile("cp.async.commit_group;" ::: "memory");
    }

    float i0 = 1.0f / l0, i1 = 1.0f / l1;
    int r0 = s0 + w * 16 + lr, r1 = r0 + 8;
    #pragma unroll
    for (int nj = 0; nj < 8; nj++) {
        int col = h * CHD + nj * 8 + 2 * lc;
        if (r0 < CS) {
            size_t off = ((size_t)b * CS + r0) * CD + col;
            *(uint32_t*)(ctxh + off) = pack2h(o[nj][0] * i0, o[nj][1] * i0);
        }
        if (r1 < CS) {
            size_t off = ((size_t)b * CS + r1) * CD + col;
            *(uint32_t*)(ctxh + off) = pack2h(o[nj][2] * i1, o[nj][3] * i1);
        }
    }
}

// ---------------------------------------------------------------------------
// Orchestration
// ---------------------------------------------------------------------------
extern "C" void kernel_launch(void* const* d_in, const int* in_sizes, int n_in,
                              void* d_out, int out_size)
{
    (void)in_sizes; (void)n_in; (void)out_size;

    const float* x     = (const float*)d_in[0];
    const float* ln1_s = (const float*)d_in[1];
    const float* ln1_b = (const float*)d_in[2];
    const float* wq    = (const float*)d_in[3];
    const float* bq    = (const float*)d_in[4];
    const float* wk    = (const float*)d_in[5];
    const float* bk    = (const float*)d_in[6];
    const float* wv    = (const float*)d_in[7];
    const float* bv    = (const float*)d_in[8];
    const float* wo    = (const float*)d_in[9];
    const float* bo    = (const float*)d_in[10];
    const float* ln2_s = (const float*)d_in[11];
    const float* ln2_b = (const float*)d_in[12];
    const float* w1    = (const float*)d_in[13];
    const float* b1    = (const float*)d_in[14];
    const float* w2    = (const float*)d_in[15];
    const float* b2    = (const float*)d_in[16];
    const float* lnf_s = (const float*)d_in[17];
    const float* lnf_b = (const float*)d_in[18];

    float *h, *bqkv;
    cudaGetSymbolAddress((void**)&h,    g_h);
    cudaGetSymbolAddress((void**)&bqkv, g_bqkv);

    __half *yh, *qkv, *ctxh, *mlph;
    cudaGetSymbolAddress((void**)&yh,   g_yh);
    cudaGetSymbolAddress((void**)&qkv,  g_qkv);
    cudaGetSymbolAddress((void**)&ctxh, g_ctxh);
    cudaGetSymbolAddress((void**)&mlph, g_mlph);

    __half *wqkvt, *wot, *w1t, *w2t;
    cudaGetSymbolAddress((void**)&wqkvt, g_wqkvt);
    cudaGetSymbolAddress((void**)&wot,  g_wot);
    cudaGetSymbolAddress((void**)&w1t,  g_w1t);
    cudaGetSymbolAddress((void**)&w2t,  g_w2t);

    cudaFuncSetAttribute(gemm_fp16<0,0,0>, cudaFuncAttributeMaxDynamicSharedMemorySize, GSMEM3);
    cudaFuncSetAttribute(gemm_fp16<0,0,2>, cudaFuncAttributeMaxDynamicSharedMemorySize, GSMEM3);
    cudaFuncSetAttribute(gemm_fp16<0,1,0>, cudaFuncAttributeMaxDynamicSharedMemorySize, GSMEM3);
    cudaFuncSetAttribute(gemm_fp16<1,0,2>, cudaFuncAttributeMaxDynamicSharedMemorySize, GSMEM3);
    cudaFuncSetAttribute(flash_attn, cudaFuncAttributeMaxDynamicSharedMemorySize, FSMEM);

    dim3 blk(256), blk192(192);

    prep_kernel<<<dim3(3457, CL), blk>>>(wq, wk, wv, wo, w1, w2,
                                         bq, bk, bv,
                                         wqkvt, wot, w1t, w2t, bqkv);

    cudaMemcpyAsync(h, x, (size_t)CBS * CD * sizeof(float),
                    cudaMemcpyDeviceToDevice);

    dim3 gqkv(QKVD / 128, CBS / 128);   // (18, 49)
    dim3 gp768(CD / 128, CBS / 128);    // (6, 49)
    dim3 gp3072(CF / 128, CBS / 128);   // (24, 49)
    dim3 gfa(NQB, CB * CH);             // (7, 96)

    for (int l = 0; l < CL; l++) {
        size_t woQ   = (size_t)l * QKVD * CD;
        size_t wo768 = (size_t)l * CD * CD;
        size_t woF   = (size_t)l * CD * CF;
        ln_h_kernel<<<CBS, blk192>>>(h, yh, ln1_s + l * CD, ln1_b + l * CD);
        gemm_fp16<0,0,2><<<gqkv, blk, GSMEM3>>>(
            yh, wqkvt + woQ, bqkv + l * QKVD, nullptr, nullptr, qkv, QKVD, CD);
        flash_attn<<<gfa, blk, FSMEM>>>(qkv, ctxh);
        gemm_fp16<0,1,0><<<gp768, blk, GSMEM3>>>(
            ctxh, wot + wo768, bo + l * CD, h, h, nullptr, CD, CD);
        ln_h_kernel<<<CBS, blk192>>>(h, yh, ln2_s + l * CD, ln2_b + l * CD);
        gemm_fp16<1,0,2><<<gp3072, blk, GSMEM3>>>(
            yh, w1t + woF, b1 + l * CF, nullptr, nullptr, mlph, CF, CD);
        gemm_fp16<0,1,0><<<gp768, blk, GSMEM3>>>(
            mlph, w2t + woF, b2 + l * CD, h, h, nullptr, CD, CF);
    }
    ln_kernel<<<CBS, blk192>>>(h, (float*)d_out, lnf_s, lnf_b);
}